// round 1
// baseline (speedup 1.0000x reference)
#include <cuda_runtime.h>
#include <math.h>

// Problem constants
#define BATCH 8
#define CIN   384
#define OCH   512
#define NTOK  2304   // 48*48

// GEMM tiling
#define BM 128
#define BN 128
#define BK 8
#define TM 8
#define TN 8
#define NTHREADS 256

// Static scratch (no allocations allowed)
__device__ float g_q [(size_t)BATCH * NTOK * OCH];   // [B][N][O]
__device__ float g_k [(size_t)BATCH * NTOK * OCH];   // [B][N][O] (token-major K)
__device__ float g_v [(size_t)BATCH * NTOK * OCH];   // [B][N][O]
__device__ float g_ao[(size_t)BATCH * NTOK * OCH];   // attention output [B][N][O]
__device__ float g_s [(size_t)BATCH * NTOK * NTOK];  // scores/probs [B][N][N]

// ---------------------------------------------------------------------------
// QKV projection: out[b][n][o] = sum_c x[b][c][n] * W[o][c] + bias[o]
// x per batch is column-major [N x C] (n contiguous), W row-major [O x C].
// ---------------------------------------------------------------------------
__global__ __launch_bounds__(NTHREADS)
void qkv_kernel(const float* __restrict__ x, const float* __restrict__ Wm,
                const float* __restrict__ bias, float* __restrict__ out)
{
    const int b    = blockIdx.z;
    const float* A = x   + (size_t)b * CIN * NTOK;
    float*       Cm= out + (size_t)b * NTOK * OCH;
    const int row0 = blockIdx.y * BM;   // token offset
    const int col0 = blockIdx.x * BN;   // out-channel offset

    __shared__ float As[BK][BM];
    __shared__ float Bs[BK][BN];

    const int tid = threadIdx.x;
    const int ty = tid / 16, tx = tid % 16;

    float acc[TM][TN];
#pragma unroll
    for (int i = 0; i < TM; i++)
#pragma unroll
        for (int j = 0; j < TN; j++) acc[i][j] = 0.f;

    for (int kt = 0; kt < CIN; kt += BK) {
        // As[c][n] = x[(kt+c)*NTOK + row0+n]  (contiguous in n -> float4)
        {
            const int c  = tid / 32;        // 0..7
            const int n4 = (tid % 32) * 4;  // 0..124
            const float4 vv = *reinterpret_cast<const float4*>(
                &A[(size_t)(kt + c) * NTOK + row0 + n4]);
            *reinterpret_cast<float4*>(&As[c][n4]) = vv;
        }
        // Bs[c][o] = W[(col0+o)*CIN + kt+c]  (transpose on store)
        {
            const int o = tid / 2;
            const int p = (tid % 2) * 4;
            const float4 vv = *reinterpret_cast<const float4*>(
                &Wm[(size_t)(col0 + o) * CIN + kt + p]);
            Bs[p + 0][o] = vv.x; Bs[p + 1][o] = vv.y;
            Bs[p + 2][o] = vv.z; Bs[p + 3][o] = vv.w;
        }
        __syncthreads();
#pragma unroll
        for (int k = 0; k < BK; k++) {
            float a[TM], bb[TN];
            *reinterpret_cast<float4*>(&a[0]) = *reinterpret_cast<const float4*>(&As[k][ty * TM]);
            *reinterpret_cast<float4*>(&a[4]) = *reinterpret_cast<const float4*>(&As[k][ty * TM + 4]);
            *reinterpret_cast<float4*>(&bb[0]) = *reinterpret_cast<const float4*>(&Bs[k][tx * TN]);
            *reinterpret_cast<float4*>(&bb[4]) = *reinterpret_cast<const float4*>(&Bs[k][tx * TN + 4]);
#pragma unroll
            for (int i = 0; i < TM; i++)
#pragma unroll
                for (int j = 0; j < TN; j++) acc[i][j] += a[i] * bb[j];
        }
        __syncthreads();
    }

#pragma unroll
    for (int i = 0; i < TM; i++) {
        const int n = row0 + ty * TM + i;
#pragma unroll
        for (int j = 0; j < TN; j++) {
            const int o = col0 + tx * TN + j;
            Cm[(size_t)n * OCH + o] = acc[i][j] + bias[o];
        }
    }
}

// ---------------------------------------------------------------------------
// C[m][n] = scale * sum_k A[m][k]*B[n][k]  (+ bias[m] if ROW_BIAS)
// A row-major [M x K], B row-major [N x K], C row-major [M x N]. Batched via z.
// ---------------------------------------------------------------------------
template <bool ROW_BIAS>
__global__ __launch_bounds__(NTHREADS)
void gemm_nt_kernel(const float* __restrict__ A, const float* __restrict__ B,
                    float* __restrict__ C, int M, int N, int K,
                    size_t sA, size_t sB, size_t sC,
                    const float* __restrict__ bias, float scale)
{
    const int b = blockIdx.z;
    const float* Ab = A + (size_t)b * sA;
    const float* Bb = B + (size_t)b * sB;
    float*       Cb = C + (size_t)b * sC;
    const int row0 = blockIdx.y * BM;
    const int col0 = blockIdx.x * BN;

    __shared__ float As[BK][BM];
    __shared__ float Bs[BK][BN];

    const int tid = threadIdx.x;
    const int ty = tid / 16, tx = tid % 16;

    float acc[TM][TN];
#pragma unroll
    for (int i = 0; i < TM; i++)
#pragma unroll
        for (int j = 0; j < TN; j++) acc[i][j] = 0.f;

    for (int kt = 0; kt < K; kt += BK) {
        {
            const int m = tid / 2;
            const int p = (tid % 2) * 4;
            const float4 vv = *reinterpret_cast<const float4*>(
                &Ab[(size_t)(row0 + m) * K + kt + p]);
            As[p + 0][m] = vv.x; As[p + 1][m] = vv.y;
            As[p + 2][m] = vv.z; As[p + 3][m] = vv.w;
        }
        {
            const int n = tid / 2;
            const int p = (tid % 2) * 4;
            const float4 vv = *reinterpret_cast<const float4*>(
                &Bb[(size_t)(col0 + n) * K + kt + p]);
            Bs[p + 0][n] = vv.x; Bs[p + 1][n] = vv.y;
            Bs[p + 2][n] = vv.z; Bs[p + 3][n] = vv.w;
        }
        __syncthreads();
#pragma unroll
        for (int k = 0; k < BK; k++) {
            float a[TM], bb[TN];
            *reinterpret_cast<float4*>(&a[0]) = *reinterpret_cast<const float4*>(&As[k][ty * TM]);
            *reinterpret_cast<float4*>(&a[4]) = *reinterpret_cast<const float4*>(&As[k][ty * TM + 4]);
            *reinterpret_cast<float4*>(&bb[0]) = *reinterpret_cast<const float4*>(&Bs[k][tx * TN]);
            *reinterpret_cast<float4*>(&bb[4]) = *reinterpret_cast<const float4*>(&Bs[k][tx * TN + 4]);
#pragma unroll
            for (int i = 0; i < TM; i++)
#pragma unroll
                for (int j = 0; j < TN; j++) acc[i][j] += a[i] * bb[j];
        }
        __syncthreads();
    }

#pragma unroll
    for (int i = 0; i < TM; i++) {
        const int m = row0 + ty * TM + i;
        const float bv = ROW_BIAS ? bias[m] : 0.f;
#pragma unroll
        for (int j = 0; j < TN; j++) {
            const int n = col0 + tx * TN + j;
            Cb[(size_t)m * N + n] = acc[i][j] * scale + bv;
        }
    }
}

// ---------------------------------------------------------------------------
// C[m][n] = sum_k A[m][k]*B[k][n]
// A row-major [M x K], B row-major [K x N], C row-major [M x N]. Batched via z.
// ---------------------------------------------------------------------------
__global__ __launch_bounds__(NTHREADS)
void gemm_nn_kernel(const float* __restrict__ A, const float* __restrict__ B,
                    float* __restrict__ C, int M, int N, int K,
                    size_t sA, size_t sB, size_t sC)
{
    const int b = blockIdx.z;
    const float* Ab = A + (size_t)b * sA;
    const float* Bb = B + (size_t)b * sB;
    float*       Cb = C + (size_t)b * sC;
    const int row0 = blockIdx.y * BM;
    const int col0 = blockIdx.x * BN;

    __shared__ float As[BK][BM];
    __shared__ float Bs[BK][BN];

    const int tid = threadIdx.x;
    const int ty = tid / 16, tx = tid % 16;

    float acc[TM][TN];
#pragma unroll
    for (int i = 0; i < TM; i++)
#pragma unroll
        for (int j = 0; j < TN; j++) acc[i][j] = 0.f;

    for (int kt = 0; kt < K; kt += BK) {
        {
            const int m = tid / 2;
            const int p = (tid % 2) * 4;
            const float4 vv = *reinterpret_cast<const float4*>(
                &Ab[(size_t)(row0 + m) * K + kt + p]);
            As[p + 0][m] = vv.x; As[p + 1][m] = vv.y;
            As[p + 2][m] = vv.z; As[p + 3][m] = vv.w;
        }
        {
            // Bs[k][n] = B[(kt+k)*N + col0+n]  (contiguous in n -> float4)
            const int k  = tid / 32;
            const int n4 = (tid % 32) * 4;
            const float4 vv = *reinterpret_cast<const float4*>(
                &Bb[(size_t)(kt + k) * N + col0 + n4]);
            *reinterpret_cast<float4*>(&Bs[k][n4]) = vv;
        }
        __syncthreads();
#pragma unroll
        for (int k = 0; k < BK; k++) {
            float a[TM], bb[TN];
            *reinterpret_cast<float4*>(&a[0]) = *reinterpret_cast<const float4*>(&As[k][ty * TM]);
            *reinterpret_cast<float4*>(&a[4]) = *reinterpret_cast<const float4*>(&As[k][ty * TM + 4]);
            *reinterpret_cast<float4*>(&bb[0]) = *reinterpret_cast<const float4*>(&Bs[k][tx * TN]);
            *reinterpret_cast<float4*>(&bb[4]) = *reinterpret_cast<const float4*>(&Bs[k][tx * TN + 4]);
#pragma unroll
            for (int i = 0; i < TM; i++)
#pragma unroll
                for (int j = 0; j < TN; j++) acc[i][j] += a[i] * bb[j];
        }
        __syncthreads();
    }

#pragma unroll
    for (int i = 0; i < TM; i++) {
        const int m = row0 + ty * TM + i;
#pragma unroll
        for (int j = 0; j < TN; j++) {
            const int n = col0 + tx * TN + j;
            Cb[(size_t)m * N + n] = acc[i][j];
        }
    }
}

// ---------------------------------------------------------------------------
// In-place row softmax. One block per row, row length = N.
// ---------------------------------------------------------------------------
__global__ __launch_bounds__(256)
void softmax_kernel(float* __restrict__ S, int N)
{
    const size_t row = blockIdx.x;
    float* p = S + row * (size_t)N;
    __shared__ float red[256];
    const int t = threadIdx.x;

    float m = -INFINITY;
    for (int i = t; i < N; i += 256) m = fmaxf(m, p[i]);
    red[t] = m; __syncthreads();
    for (int s = 128; s > 0; s >>= 1) {
        if (t < s) red[t] = fmaxf(red[t], red[t + s]);
        __syncthreads();
    }
    m = red[0];
    __syncthreads();

    float sum = 0.f;
    for (int i = t; i < N; i += 256) {
        const float e = __expf(p[i] - m);
        p[i] = e;
        sum += e;
    }
    red[t] = sum; __syncthreads();
    for (int s = 128; s > 0; s >>= 1) {
        if (t < s) red[t] += red[t + s];
        __syncthreads();
    }
    const float inv = 1.0f / red[0];
    __syncthreads();
    for (int i = t; i < N; i += 256) p[i] *= inv;
}

// ---------------------------------------------------------------------------
extern "C" void kernel_launch(void* const* d_in, const int* in_sizes, int n_in,
                              void* d_out, int out_size)
{
    const float* x  = (const float*)d_in[0];
    const float* Wq = (const float*)d_in[1];
    const float* bq = (const float*)d_in[2];
    const float* Wk = (const float*)d_in[3];
    const float* bk = (const float*)d_in[4];
    const float* Wv = (const float*)d_in[5];
    const float* bv = (const float*)d_in[6];
    const float* Wo = (const float*)d_in[7];
    const float* bo = (const float*)d_in[8];
    float* out = (float*)d_out;

    float *q, *k, *v, *ao, *s;
    cudaGetSymbolAddress((void**)&q,  g_q);
    cudaGetSymbolAddress((void**)&k,  g_k);
    cudaGetSymbolAddress((void**)&v,  g_v);
    cudaGetSymbolAddress((void**)&ao, g_ao);
    cudaGetSymbolAddress((void**)&s,  g_s);

    const dim3 blk(NTHREADS);
    const size_t sQKV = (size_t)NTOK * OCH;   // per-batch stride of Q/K/V/AO
    const size_t sS   = (size_t)NTOK * NTOK;  // per-batch stride of scores
    const float scale = 0.044194173824159216f; // 1/sqrt(512)

    // 1) QKV projections  (grid: 4 x 18 x 8)
    {
        dim3 g(OCH / BN, NTOK / BM, BATCH);
        qkv_kernel<<<g, blk>>>(x, Wq, bq, q);
        qkv_kernel<<<g, blk>>>(x, Wk, bk, k);
        qkv_kernel<<<g, blk>>>(x, Wv, bv, v);
    }
    // 2) S = scale * Q @ K^T   (grid: 18 x 18 x 8)
    {
        dim3 g(NTOK / BN, NTOK / BM, BATCH);
        gemm_nt_kernel<false><<<g, blk>>>(q, k, s, NTOK, NTOK, OCH,
                                          sQKV, sQKV, sS, nullptr, scale);
    }
    // 3) softmax rows
    softmax_kernel<<<BATCH * NTOK, 256>>>(s, NTOK);

    // 4) AO = P @ V            (grid: 4 x 18 x 8)
    {
        dim3 g(OCH / BN, NTOK / BM, BATCH);
        gemm_nn_kernel<<<g, blk>>>(s, v, ao, NTOK, OCH, NTOK, sS, sQKV, sQKV);
    }
    // 5) out = Wo @ AO^T + bo  -> [B, 512, 2304] row-major (= [B,512,48,48])
    {
        dim3 g(NTOK / BN, OCH / BM, BATCH);
        gemm_nt_kernel<true><<<g, blk>>>(Wo, ao, out, OCH, NTOK, OCH,
                                         0, sQKV, (size_t)OCH * NTOK, bo, 1.0f);
    }
}

// round 2
// speedup vs baseline: 1.6232x; 1.6232x over previous
#include <cuda_runtime.h>
#include <math.h>
#include <stdint.h>

// Problem constants
#define BATCH 8
#define CIN   384
#define OCH   512
#define NTOK  2304   // 48*48

// GEMM tiling
#define BM 128
#define BN 128
#define BK 16
#define PAD 8
#define SAS (BM + PAD)
#define SBS (BN + PAD)
#define NTHREADS 256

// Static scratch (no allocations allowed)
__device__ float g_q [(size_t)BATCH * NTOK * OCH];   // [B][N][O]
__device__ float g_k [(size_t)BATCH * NTOK * OCH];   // [B][N][O]
__device__ float g_v [(size_t)BATCH * NTOK * OCH];   // [B][N][O]
__device__ float g_ao[(size_t)BATCH * NTOK * OCH];   // [B][N][O]
__device__ float g_s [(size_t)BATCH * NTOK * NTOK];  // [B][N][N]

// ---------------------------------------------------------------------------
// Helpers
// ---------------------------------------------------------------------------
__device__ __forceinline__ float to_tf32(float x) {
    uint32_t u;
    asm("cvt.rna.tf32.f32 %0, %1;" : "=r"(u) : "f"(x));
    return __uint_as_float(u);
}
__device__ __forceinline__ float4 cvt4(float4 v) {
    v.x = to_tf32(v.x); v.y = to_tf32(v.y);
    v.z = to_tf32(v.z); v.w = to_tf32(v.w);
    return v;
}

__device__ __forceinline__ void mma8(float c[4], const uint32_t a[4], const uint32_t b[2]) {
    asm volatile(
        "mma.sync.aligned.m16n8k8.row.col.f32.tf32.tf32.f32 "
        "{%0,%1,%2,%3}, {%4,%5,%6,%7}, {%8,%9}, {%0,%1,%2,%3};"
        : "+f"(c[0]), "+f"(c[1]), "+f"(c[2]), "+f"(c[3])
        : "r"(a[0]), "r"(a[1]), "r"(a[2]), "r"(a[3]), "r"(b[0]), "r"(b[1]));
}

// Warp-level compute of one 128x128x16 tile step (each warp: 64x32).
__device__ __forceinline__ void compute_tile(
    const float (*As)[SAS], const float (*Bs)[SBS],
    float acc[4][4][4], int wm, int wn, int g, int t4)
{
#pragma unroll
    for (int ks = 0; ks < 2; ks++) {
        const int kb = ks * 8;
        uint32_t ra[4][4], rb[4][2];
#pragma unroll
        for (int i = 0; i < 4; i++) {
            const int m = wm + i * 16 + g;
            ra[i][0] = __float_as_uint(As[kb + t4    ][m    ]);
            ra[i][1] = __float_as_uint(As[kb + t4    ][m + 8]);
            ra[i][2] = __float_as_uint(As[kb + t4 + 4][m    ]);
            ra[i][3] = __float_as_uint(As[kb + t4 + 4][m + 8]);
        }
#pragma unroll
        for (int j = 0; j < 4; j++) {
            const int n = wn + j * 8 + g;
            rb[j][0] = __float_as_uint(Bs[kb + t4    ][n]);
            rb[j][1] = __float_as_uint(Bs[kb + t4 + 4][n]);
        }
#pragma unroll
        for (int i = 0; i < 4; i++)
#pragma unroll
            for (int j = 0; j < 4; j++)
                mma8(acc[i][j], ra[i], rb[j]);
    }
}

// ---------------------------------------------------------------------------
// QKV projection: out[b][n][o] = sum_c x[b][c][n] * W[o][c] + bias[o]
// ---------------------------------------------------------------------------
__global__ __launch_bounds__(NTHREADS)
void qkv_kernel(const float* __restrict__ x, const float* __restrict__ Wm,
                const float* __restrict__ bias, float* __restrict__ out)
{
    const int b    = blockIdx.z;
    const float* A = x   + (size_t)b * CIN * NTOK;
    float*       Cm= out + (size_t)b * NTOK * OCH;
    const int row0 = blockIdx.y * BM;   // token offset (M dim)
    const int col0 = blockIdx.x * BN;   // out-channel offset (N dim)

    __shared__ float As[2][BK][SAS];
    __shared__ float Bs[2][BK][SBS];

    const int tid  = threadIdx.x;
    const int warp = tid >> 5, lane = tid & 31;
    const int g = lane >> 2, t4 = lane & 3;
    const int wm = (warp >> 2) * 64, wn = (warp & 3) * 32;

    // A loader (contiguous inner): r = c index (0..15), c8 = token offset
    const int la_r  = tid >> 4;
    const int la_c8 = (tid & 15) * 8;
    // B loader (scatter): o row, p k-offset
    const int lb_o = tid >> 1;
    const int lb_p = (tid & 1) * 8;

    float acc[4][4][4];
#pragma unroll
    for (int i = 0; i < 4; i++)
#pragma unroll
        for (int j = 0; j < 4; j++)
#pragma unroll
            for (int q = 0; q < 4; q++) acc[i][j][q] = 0.f;

    const int T = CIN / BK;
    // preload tile 0
    {
        float4 a0 = cvt4(*reinterpret_cast<const float4*>(&A[(size_t)la_r * NTOK + row0 + la_c8]));
        float4 a1 = cvt4(*reinterpret_cast<const float4*>(&A[(size_t)la_r * NTOK + row0 + la_c8 + 4]));
        *reinterpret_cast<float4*>(&As[0][la_r][la_c8])     = a0;
        *reinterpret_cast<float4*>(&As[0][la_r][la_c8 + 4]) = a1;
        float4 b0 = *reinterpret_cast<const float4*>(&Wm[(size_t)(col0 + lb_o) * CIN + lb_p]);
        float4 b1 = *reinterpret_cast<const float4*>(&Wm[(size_t)(col0 + lb_o) * CIN + lb_p + 4]);
        Bs[0][lb_p + 0][lb_o] = to_tf32(b0.x); Bs[0][lb_p + 1][lb_o] = to_tf32(b0.y);
        Bs[0][lb_p + 2][lb_o] = to_tf32(b0.z); Bs[0][lb_p + 3][lb_o] = to_tf32(b0.w);
        Bs[0][lb_p + 4][lb_o] = to_tf32(b1.x); Bs[0][lb_p + 5][lb_o] = to_tf32(b1.y);
        Bs[0][lb_p + 6][lb_o] = to_tf32(b1.z); Bs[0][lb_p + 7][lb_o] = to_tf32(b1.w);
    }
    __syncthreads();

    int cur = 0;
    for (int t = 0; t < T; t++) {
        float4 a0, a1, b0, b1;
        const bool more = (t + 1 < T);
        if (more) {
            const int kt = (t + 1) * BK;
            a0 = *reinterpret_cast<const float4*>(&A[(size_t)(kt + la_r) * NTOK + row0 + la_c8]);
            a1 = *reinterpret_cast<const float4*>(&A[(size_t)(kt + la_r) * NTOK + row0 + la_c8 + 4]);
            b0 = *reinterpret_cast<const float4*>(&Wm[(size_t)(col0 + lb_o) * CIN + kt + lb_p]);
            b1 = *reinterpret_cast<const float4*>(&Wm[(size_t)(col0 + lb_o) * CIN + kt + lb_p + 4]);
        }
        compute_tile(As[cur], Bs[cur], acc, wm, wn, g, t4);
        if (more) {
            const int nxt = cur ^ 1;
            *reinterpret_cast<float4*>(&As[nxt][la_r][la_c8])     = cvt4(a0);
            *reinterpret_cast<float4*>(&As[nxt][la_r][la_c8 + 4]) = cvt4(a1);
            Bs[nxt][lb_p + 0][lb_o] = to_tf32(b0.x); Bs[nxt][lb_p + 1][lb_o] = to_tf32(b0.y);
            Bs[nxt][lb_p + 2][lb_o] = to_tf32(b0.z); Bs[nxt][lb_p + 3][lb_o] = to_tf32(b0.w);
            Bs[nxt][lb_p + 4][lb_o] = to_tf32(b1.x); Bs[nxt][lb_p + 5][lb_o] = to_tf32(b1.y);
            Bs[nxt][lb_p + 6][lb_o] = to_tf32(b1.z); Bs[nxt][lb_p + 7][lb_o] = to_tf32(b1.w);
            __syncthreads();
        }
        cur ^= 1;
    }

    // epilogue: column bias
#pragma unroll
    for (int i = 0; i < 4; i++) {
        const int r0 = row0 + wm + i * 16 + g;
#pragma unroll
        for (int j = 0; j < 4; j++) {
            const int c = col0 + wn + j * 8 + 2 * t4;
            const float bv0 = bias[c], bv1 = bias[c + 1];
            float2 v0 = make_float2(acc[i][j][0] + bv0, acc[i][j][1] + bv1);
            float2 v1 = make_float2(acc[i][j][2] + bv0, acc[i][j][3] + bv1);
            *reinterpret_cast<float2*>(&Cm[(size_t)r0 * OCH + c])       = v0;
            *reinterpret_cast<float2*>(&Cm[(size_t)(r0 + 8) * OCH + c]) = v1;
        }
    }
}

// ---------------------------------------------------------------------------
// C[m][n] = scale * sum_k A[m][k]*B[n][k]  (+ bias[m] if ROW_BIAS)
// ---------------------------------------------------------------------------
template <bool ROW_BIAS>
__global__ __launch_bounds__(NTHREADS)
void gemm_nt_kernel(const float* __restrict__ A, const float* __restrict__ B,
                    float* __restrict__ C, int N, int K,
                    size_t sA, size_t sB, size_t sC,
                    const float* __restrict__ bias, float scale)
{
    const int b = blockIdx.z;
    const float* Ab = A + (size_t)b * sA;
    const float* Bb = B + (size_t)b * sB;
    float*       Cb = C + (size_t)b * sC;
    const int row0 = blockIdx.y * BM;
    const int col0 = blockIdx.x * BN;

    __shared__ float As[2][BK][SAS];
    __shared__ float Bs[2][BK][SBS];

    const int tid  = threadIdx.x;
    const int warp = tid >> 5, lane = tid & 31;
    const int g = lane >> 2, t4 = lane & 3;
    const int wm = (warp >> 2) * 64, wn = (warp & 3) * 32;

    const int lm = tid >> 1;          // row for both loaders (0..127)
    const int lp = (tid & 1) * 8;     // k offset

    float acc[4][4][4];
#pragma unroll
    for (int i = 0; i < 4; i++)
#pragma unroll
        for (int j = 0; j < 4; j++)
#pragma unroll
            for (int q = 0; q < 4; q++) acc[i][j][q] = 0.f;

    const int T = K / BK;
    {
        float4 a0 = *reinterpret_cast<const float4*>(&Ab[(size_t)(row0 + lm) * K + lp]);
        float4 a1 = *reinterpret_cast<const float4*>(&Ab[(size_t)(row0 + lm) * K + lp + 4]);
        float4 b0 = *reinterpret_cast<const float4*>(&Bb[(size_t)(col0 + lm) * K + lp]);
        float4 b1 = *reinterpret_cast<const float4*>(&Bb[(size_t)(col0 + lm) * K + lp + 4]);
        As[0][lp + 0][lm] = to_tf32(a0.x); As[0][lp + 1][lm] = to_tf32(a0.y);
        As[0][lp + 2][lm] = to_tf32(a0.z); As[0][lp + 3][lm] = to_tf32(a0.w);
        As[0][lp + 4][lm] = to_tf32(a1.x); As[0][lp + 5][lm] = to_tf32(a1.y);
        As[0][lp + 6][lm] = to_tf32(a1.z); As[0][lp + 7][lm] = to_tf32(a1.w);
        Bs[0][lp + 0][lm] = to_tf32(b0.x); Bs[0][lp + 1][lm] = to_tf32(b0.y);
        Bs[0][lp + 2][lm] = to_tf32(b0.z); Bs[0][lp + 3][lm] = to_tf32(b0.w);
        Bs[0][lp + 4][lm] = to_tf32(b1.x); Bs[0][lp + 5][lm] = to_tf32(b1.y);
        Bs[0][lp + 6][lm] = to_tf32(b1.z); Bs[0][lp + 7][lm] = to_tf32(b1.w);
    }
    __syncthreads();

    int cur = 0;
    for (int t = 0; t < T; t++) {
        float4 a0, a1, b0, b1;
        const bool more = (t + 1 < T);
        if (more) {
            const int kt = (t + 1) * BK;
            a0 = *reinterpret_cast<const float4*>(&Ab[(size_t)(row0 + lm) * K + kt + lp]);
            a1 = *reinterpret_cast<const float4*>(&Ab[(size_t)(row0 + lm) * K + kt + lp + 4]);
            b0 = *reinterpret_cast<const float4*>(&Bb[(size_t)(col0 + lm) * K + kt + lp]);
            b1 = *reinterpret_cast<const float4*>(&Bb[(size_t)(col0 + lm) * K + kt + lp + 4]);
        }
        compute_tile(As[cur], Bs[cur], acc, wm, wn, g, t4);
        if (more) {
            const int nxt = cur ^ 1;
            As[nxt][lp + 0][lm] = to_tf32(a0.x); As[nxt][lp + 1][lm] = to_tf32(a0.y);
            As[nxt][lp + 2][lm] = to_tf32(a0.z); As[nxt][lp + 3][lm] = to_tf32(a0.w);
            As[nxt][lp + 4][lm] = to_tf32(a1.x); As[nxt][lp + 5][lm] = to_tf32(a1.y);
            As[nxt][lp + 6][lm] = to_tf32(a1.z); As[nxt][lp + 7][lm] = to_tf32(a1.w);
            Bs[nxt][lp + 0][lm] = to_tf32(b0.x); Bs[nxt][lp + 1][lm] = to_tf32(b0.y);
            Bs[nxt][lp + 2][lm] = to_tf32(b0.z); Bs[nxt][lp + 3][lm] = to_tf32(b0.w);
            Bs[nxt][lp + 4][lm] = to_tf32(b1.x); Bs[nxt][lp + 5][lm] = to_tf32(b1.y);
            Bs[nxt][lp + 6][lm] = to_tf32(b1.z); Bs[nxt][lp + 7][lm] = to_tf32(b1.w);
            __syncthreads();
        }
        cur ^= 1;
    }

#pragma unroll
    for (int i = 0; i < 4; i++) {
        const int r0 = row0 + wm + i * 16 + g;
        const float bv0 = ROW_BIAS ? bias[r0] : 0.f;
        const float bv1 = ROW_BIAS ? bias[r0 + 8] : 0.f;
#pragma unroll
        for (int j = 0; j < 4; j++) {
            const int c = col0 + wn + j * 8 + 2 * t4;
            float2 v0 = make_float2(acc[i][j][0] * scale + bv0, acc[i][j][1] * scale + bv0);
            float2 v1 = make_float2(acc[i][j][2] * scale + bv1, acc[i][j][3] * scale + bv1);
            *reinterpret_cast<float2*>(&Cb[(size_t)r0 * N + c])       = v0;
            *reinterpret_cast<float2*>(&Cb[(size_t)(r0 + 8) * N + c]) = v1;
        }
    }
}

// ---------------------------------------------------------------------------
// C[m][n] = sum_k A[m][k]*B[k][n]   (A row-major MxK, B row-major KxN)
// ---------------------------------------------------------------------------
__global__ __launch_bounds__(NTHREADS)
void gemm_nn_kernel(const float* __restrict__ A, const float* __restrict__ B,
                    float* __restrict__ C, int N, int K,
                    size_t sA, size_t sB, size_t sC)
{
    const int b = blockIdx.z;
    const float* Ab = A + (size_t)b * sA;
    const float* Bb = B + (size_t)b * sB;
    float*       Cb = C + (size_t)b * sC;
    const int row0 = blockIdx.y * BM;
    const int col0 = blockIdx.x * BN;

    __shared__ float As[2][BK][SAS];
    __shared__ float Bs[2][BK][SBS];

    const int tid  = threadIdx.x;
    const int warp = tid >> 5, lane = tid & 31;
    const int g = lane >> 2, t4 = lane & 3;
    const int wm = (warp >> 2) * 64, wn = (warp & 3) * 32;

    const int la_m = tid >> 1;
    const int la_p = (tid & 1) * 8;
    const int lb_r  = tid >> 4;
    const int lb_c8 = (tid & 15) * 8;

    float acc[4][4][4];
#pragma unroll
    for (int i = 0; i < 4; i++)
#pragma unroll
        for (int j = 0; j < 4; j++)
#pragma unroll
            for (int q = 0; q < 4; q++) acc[i][j][q] = 0.f;

    const int T = K / BK;
    {
        float4 a0 = *reinterpret_cast<const float4*>(&Ab[(size_t)(row0 + la_m) * K + la_p]);
        float4 a1 = *reinterpret_cast<const float4*>(&Ab[(size_t)(row0 + la_m) * K + la_p + 4]);
        As[0][la_p + 0][la_m] = to_tf32(a0.x); As[0][la_p + 1][la_m] = to_tf32(a0.y);
        As[0][la_p + 2][la_m] = to_tf32(a0.z); As[0][la_p + 3][la_m] = to_tf32(a0.w);
        As[0][la_p + 4][la_m] = to_tf32(a1.x); As[0][la_p + 5][la_m] = to_tf32(a1.y);
        As[0][la_p + 6][la_m] = to_tf32(a1.z); As[0][la_p + 7][la_m] = to_tf32(a1.w);
        float4 b0 = cvt4(*reinterpret_cast<const float4*>(&Bb[(size_t)lb_r * N + col0 + lb_c8]));
        float4 b1 = cvt4(*reinterpret_cast<const float4*>(&Bb[(size_t)lb_r * N + col0 + lb_c8 + 4]));
        *reinterpret_cast<float4*>(&Bs[0][lb_r][lb_c8])     = b0;
        *reinterpret_cast<float4*>(&Bs[0][lb_r][lb_c8 + 4]) = b1;
    }
    __syncthreads();

    int cur = 0;
    for (int t = 0; t < T; t++) {
        float4 a0, a1, b0, b1;
        const bool more = (t + 1 < T);
        if (more) {
            const int kt = (t + 1) * BK;
            a0 = *reinterpret_cast<const float4*>(&Ab[(size_t)(row0 + la_m) * K + kt + la_p]);
            a1 = *reinterpret_cast<const float4*>(&Ab[(size_t)(row0 + la_m) * K + kt + la_p + 4]);
            b0 = *reinterpret_cast<const float4*>(&Bb[(size_t)(kt + lb_r) * N + col0 + lb_c8]);
            b1 = *reinterpret_cast<const float4*>(&Bb[(size_t)(kt + lb_r) * N + col0 + lb_c8 + 4]);
        }
        compute_tile(As[cur], Bs[cur], acc, wm, wn, g, t4);
        if (more) {
            const int nxt = cur ^ 1;
            As[nxt][la_p + 0][la_m] = to_tf32(a0.x); As[nxt][la_p + 1][la_m] = to_tf32(a0.y);
            As[nxt][la_p + 2][la_m] = to_tf32(a0.z); As[nxt][la_p + 3][la_m] = to_tf32(a0.w);
            As[nxt][la_p + 4][la_m] = to_tf32(a1.x); As[nxt][la_p + 5][la_m] = to_tf32(a1.y);
            As[nxt][la_p + 6][la_m] = to_tf32(a1.z); As[nxt][la_p + 7][la_m] = to_tf32(a1.w);
            *reinterpret_cast<float4*>(&Bs[nxt][lb_r][lb_c8])     = cvt4(b0);
            *reinterpret_cast<float4*>(&Bs[nxt][lb_r][lb_c8 + 4]) = cvt4(b1);
            __syncthreads();
        }
        cur ^= 1;
    }

#pragma unroll
    for (int i = 0; i < 4; i++) {
        const int r0 = row0 + wm + i * 16 + g;
#pragma unroll
        for (int j = 0; j < 4; j++) {
            const int c = col0 + wn + j * 8 + 2 * t4;
            float2 v0 = make_float2(acc[i][j][0], acc[i][j][1]);
            float2 v1 = make_float2(acc[i][j][2], acc[i][j][3]);
            *reinterpret_cast<float2*>(&Cb[(size_t)r0 * N + c])       = v0;
            *reinterpret_cast<float2*>(&Cb[(size_t)(r0 + 8) * N + c]) = v1;
        }
    }
}

// ---------------------------------------------------------------------------
// In-place row softmax. One block per row, row length = N.
// ---------------------------------------------------------------------------
__global__ __launch_bounds__(256)
void softmax_kernel(float* __restrict__ S, int N)
{
    const size_t row = blockIdx.x;
    float* p = S + row * (size_t)N;
    __shared__ float red[256];
    const int t = threadIdx.x;

    float m = -INFINITY;
    for (int i = t; i < N; i += 256) m = fmaxf(m, p[i]);
    red[t] = m; __syncthreads();
    for (int s = 128; s > 0; s >>= 1) {
        if (t < s) red[t] = fmaxf(red[t], red[t + s]);
        __syncthreads();
    }
    m = red[0];
    __syncthreads();

    float sum = 0.f;
    for (int i = t; i < N; i += 256) {
        const float e = __expf(p[i] - m);
        p[i] = e;
        sum += e;
    }
    red[t] = sum; __syncthreads();
    for (int s = 128; s > 0; s >>= 1) {
        if (t < s) red[t] += red[t + s];
        __syncthreads();
    }
    const float inv = 1.0f / red[0];
    __syncthreads();
    for (int i = t; i < N; i += 256) p[i] *= inv;
}

// ---------------------------------------------------------------------------
extern "C" void kernel_launch(void* const* d_in, const int* in_sizes, int n_in,
                              void* d_out, int out_size)
{
    const float* x  = (const float*)d_in[0];
    const float* Wq = (const float*)d_in[1];
    const float* bq = (const float*)d_in[2];
    const float* Wk = (const float*)d_in[3];
    const float* bk = (const float*)d_in[4];
    const float* Wv = (const float*)d_in[5];
    const float* bv = (const float*)d_in[6];
    const float* Wo = (const float*)d_in[7];
    const float* bo = (const float*)d_in[8];
    float* out = (float*)d_out;

    float *q, *k, *v, *ao, *s;
    cudaGetSymbolAddress((void**)&q,  g_q);
    cudaGetSymbolAddress((void**)&k,  g_k);
    cudaGetSymbolAddress((void**)&v,  g_v);
    cudaGetSymbolAddress((void**)&ao, g_ao);
    cudaGetSymbolAddress((void**)&s,  g_s);

    const dim3 blk(NTHREADS);
    const size_t sQKV = (size_t)NTOK * OCH;
    const size_t sS   = (size_t)NTOK * NTOK;
    const float scale = 0.044194173824159216f; // 1/sqrt(512)

    // 1) QKV projections
    {
        dim3 g(OCH / BN, NTOK / BM, BATCH);
        qkv_kernel<<<g, blk>>>(x, Wq, bq, q);
        qkv_kernel<<<g, blk>>>(x, Wk, bk, k);
        qkv_kernel<<<g, blk>>>(x, Wv, bv, v);
    }
    // 2) S = scale * Q @ K^T
    {
        dim3 g(NTOK / BN, NTOK / BM, BATCH);
        gemm_nt_kernel<false><<<g, blk>>>(q, k, s, NTOK, OCH,
                                          sQKV, sQKV, sS, nullptr, scale);
    }
    // 3) softmax rows
    softmax_kernel<<<BATCH * NTOK, 256>>>(s, NTOK);

    // 4) AO = P @ V
    {
        dim3 g(OCH / BN, NTOK / BM, BATCH);
        gemm_nn_kernel<<<g, blk>>>(s, v, ao, OCH, NTOK, sS, sQKV, sQKV);
    }
    // 5) out = Wo @ AO^T + bo  -> [B, 512, 2304] row-major
    {
        dim3 g(NTOK / BN, OCH / BM, BATCH);
        gemm_nt_kernel<true><<<g, blk>>>(Wo, ao, out, NTOK, OCH,
                                         0, sQKV, (size_t)OCH * NTOK, bo, 1.0f);
    }
}

// round 4
// speedup vs baseline: 5.2188x; 3.2152x over previous
#include <cuda_runtime.h>
#include <cuda_fp16.h>
#include <math.h>
#include <stdint.h>

// Problem constants
#define BATCH 8
#define CIN   384
#define OCH   512
#define NTOK  2304   // 48*48

#define NTHREADS 256
// Block tile 128x128, K-tile = 32 halves
#define SNT 40    // NT smem tile row stride (halves): [128 r][40]
#define STR 136   // TR smem tile row stride (halves): [32 k][136]

// Static scratch (no allocations allowed)
__device__ __half g_q [(size_t)BATCH * NTOK * OCH];   // [B][tok][och]
__device__ __half g_k [(size_t)BATCH * NTOK * OCH];   // [B][tok][och]
__device__ __half g_vt[(size_t)BATCH * OCH * NTOK];   // [B][och][tok]  (V transposed)
__device__ __half g_p [(size_t)BATCH * NTOK * NTOK];  // probs [B][tok][tok]
__device__ __half g_ao[(size_t)BATCH * NTOK * OCH];   // [B][tok][och]
__device__ float  g_s [(size_t)BATCH * NTOK * NTOK];  // scores fp32

// ---------------------------------------------------------------------------
// Helpers
// ---------------------------------------------------------------------------
__device__ __forceinline__ uint32_t smem_u32(const void* p) {
    uint32_t a;
    asm("{ .reg .u64 t; cvta.to.shared.u64 t, %1; cvt.u32.u64 %0, t; }" : "=r"(a) : "l"(p));
    return a;
}
__device__ __forceinline__ uint32_t pack_h2(float x, float y) {
    __half2 h = __floats2half2_rn(x, y);
    return *reinterpret_cast<uint32_t*>(&h);
}
__device__ __forceinline__ void ldsm4(uint32_t r[4], uint32_t addr) {
    asm volatile("ldmatrix.sync.aligned.m8n8.x4.shared.b16 {%0,%1,%2,%3}, [%4];"
                 : "=r"(r[0]), "=r"(r[1]), "=r"(r[2]), "=r"(r[3]) : "r"(addr));
}
__device__ __forceinline__ void ldsm4t(uint32_t r[4], uint32_t addr) {
    asm volatile("ldmatrix.sync.aligned.m8n8.x4.trans.shared.b16 {%0,%1,%2,%3}, [%4];"
                 : "=r"(r[0]), "=r"(r[1]), "=r"(r[2]), "=r"(r[3]) : "r"(addr));
}
__device__ __forceinline__ void mma16816(float c[4], const uint32_t a[4],
                                         uint32_t b0, uint32_t b1) {
    asm volatile(
        "mma.sync.aligned.m16n8k16.row.col.f32.f16.f16.f32 "
        "{%0,%1,%2,%3}, {%4,%5,%6,%7}, {%8,%9}, {%0,%1,%2,%3};"
        : "+f"(c[0]), "+f"(c[1]), "+f"(c[2]), "+f"(c[3])
        : "r"(a[0]), "r"(a[1]), "r"(a[2]), "r"(a[3]), "r"(b0), "r"(b1));
}

// ---------------------------------------------------------------------------
// Operand staging. MODE: 0 = f16 row-major [r][k]; 1 = f32 row-major [r][k];
//                        2 = f32 transposed source [k][r] (x layout).
// NT smem tile: [128][SNT] halves (row r, col k). TR smem tile: [32][STR].
// ---------------------------------------------------------------------------
template <int MODE>
__device__ __forceinline__ void stage_load(uint4 R[4], const void* src, int ld,
                                           int r0, int kt, int tid)
{
    if (MODE == 0) {
        const __half* S = (const __half*)src;
#pragma unroll
        for (int i = 0; i < 2; i++) {
            const int idx = tid + i * 256;
            const int r = idx >> 2, c8 = (idx & 3) * 8;
            R[i] = *reinterpret_cast<const uint4*>(&S[(size_t)(r0 + r) * ld + kt + c8]);
        }
    } else if (MODE == 1) {
        const float* S = (const float*)src;
#pragma unroll
        for (int i = 0; i < 4; i++) {
            const int idx = tid + i * 256;
            const int r = idx >> 3, c4 = (idx & 7) * 4;
            R[i] = *reinterpret_cast<const uint4*>(&S[(size_t)(r0 + r) * ld + kt + c4]);
        }
    } else {
        const float* S = (const float*)src;
#pragma unroll
        for (int i = 0; i < 4; i++) {
            const int idx = tid + i * 256;
            const int k = idx >> 5, m4 = (idx & 31) * 4;
            R[i] = *reinterpret_cast<const uint4*>(&S[(size_t)(kt + k) * ld + r0 + m4]);
        }
    }
}

template <int MODE>
__device__ __forceinline__ void stage_store(const uint4 R[4], __half* tile, int tid)
{
    if (MODE == 0) {
#pragma unroll
        for (int i = 0; i < 2; i++) {
            const int idx = tid + i * 256;
            const int r = idx >> 2, c8 = (idx & 3) * 8;
            *reinterpret_cast<uint4*>(&tile[r * SNT + c8]) = R[i];
        }
    } else if (MODE == 1) {
#pragma unroll
        for (int i = 0; i < 4; i++) {
            const int idx = tid + i * 256;
            const int r = idx >> 3, c4 = (idx & 7) * 4;
            const float4 f = *reinterpret_cast<const float4*>(&R[i]);
            uint2 v; v.x = pack_h2(f.x, f.y); v.y = pack_h2(f.z, f.w);
            *reinterpret_cast<uint2*>(&tile[r * SNT + c4]) = v;
        }
    } else {
#pragma unroll
        for (int i = 0; i < 4; i++) {
            const int idx = tid + i * 256;
            const int k = idx >> 5, m4 = (idx & 31) * 4;
            const float4 f = *reinterpret_cast<const float4*>(&R[i]);
            uint2 v; v.x = pack_h2(f.x, f.y); v.y = pack_h2(f.z, f.w);
            *reinterpret_cast<uint2*>(&tile[k * STR + m4]) = v;
        }
    }
}

// ---------------------------------------------------------------------------
// One 128x128x32 tile step. Warp tile 64x32 via m16n8k16 + ldmatrix.
// ---------------------------------------------------------------------------
template <int AM, int BM>
__device__ __forceinline__ void compute_bk(uint32_t sa, uint32_t sb,
                                           float acc[4][4][4], int lane, int wm, int wn)
{
    constexpr bool ATR = (AM == 2), BTR = (BM == 2);
#pragma unroll
    for (int ks = 0; ks < 32; ks += 16) {
        uint32_t a[4][4];
#pragma unroll
        for (int mb = 0; mb < 4; mb++) {
            if (!ATR) {
                const int row = wm + mb * 16 + (lane & 15);
                const int col = ks + ((lane >> 4) << 3);
                ldsm4(a[mb], sa + (row * SNT + col) * 2);
            } else {
                const int k   = ks + (lane & 7) + ((lane & 16) >> 1);
                const int col = wm + mb * 16 + (lane & 8);
                ldsm4t(a[mb], sa + (k * STR + col) * 2);
            }
        }
        uint32_t bfr[2][4];
#pragma unroll
        for (int nb2 = 0; nb2 < 2; nb2++) {
            if (!BTR) {
                const int row = wn + nb2 * 16 + (lane & 15);
                const int col = ks + ((lane >> 4) << 3);
                ldsm4(bfr[nb2], sb + (row * SNT + col) * 2);
            } else {
                const int k   = ks + (lane & 7) + (lane & 8);
                const int col = wn + nb2 * 16 + ((lane & 16) >> 1);
                ldsm4t(bfr[nb2], sb + (k * STR + col) * 2);
            }
        }
#pragma unroll
        for (int mb = 0; mb < 4; mb++)
#pragma unroll
            for (int nb = 0; nb < 4; nb++) {
                uint32_t b0, b1;
                if (!BTR) { b0 = bfr[nb >> 1][nb & 1];       b1 = bfr[nb >> 1][(nb & 1) + 2]; }
                else      { b0 = bfr[nb >> 1][2 * (nb & 1)]; b1 = bfr[nb >> 1][2 * (nb & 1) + 1]; }
                mma16816(acc[mb][nb], a[mb], b0, b1);
            }
    }
}

// ---------------------------------------------------------------------------
// Universal batched half-precision GEMM:
//   C[m][n] = scale * sum_k opA(A)[m][k] * opB(B)[n][k] + bias
// AM/BM: operand modes (see stage_load). OUTH: 1 = half output, 0 = fp32.
// BIAS: 0 none, 1 row (bias[m]), 2 col (bias[n]).
// ---------------------------------------------------------------------------
template <int AM, int BM, int OUTH, int BIAS>
__global__ __launch_bounds__(NTHREADS)
void hgemm(const void* __restrict__ A, const void* __restrict__ B, void* __restrict__ C,
           int K, int ldA, int ldB, int ldC,
           size_t sA, size_t sB, size_t sC,
           const float* __restrict__ bias, float scale)
{
    __shared__ __align__(16) __half smA[2][5120];
    __shared__ __align__(16) __half smB[2][5120];

    const int tid = threadIdx.x;
    const int warp = tid >> 5, lane = tid & 31;
    const int wm = (warp >> 2) * 64, wn = (warp & 3) * 32;
    const int b = blockIdx.z;
    const int row0 = blockIdx.y * 128;
    const int col0 = blockIdx.x * 128;

    const void* Ab = (AM == 0) ? (const void*)((const __half*)A + (size_t)b * sA)
                               : (const void*)((const float*)A + (size_t)b * sA);
    const void* Bb = (BM == 0) ? (const void*)((const __half*)B + (size_t)b * sB)
                               : (const void*)((const float*)B + (size_t)b * sB);

    float acc[4][4][4];
#pragma unroll
    for (int i = 0; i < 4; i++)
#pragma unroll
        for (int j = 0; j < 4; j++)
#pragma unroll
            for (int q = 0; q < 4; q++) acc[i][j][q] = 0.f;

    uint4 ra[4], rb[4];
    stage_load<AM>(ra, Ab, ldA, row0, 0, tid);
    stage_load<BM>(rb, Bb, ldB, col0, 0, tid);
    stage_store<AM>(ra, smA[0], tid);
    stage_store<BM>(rb, smB[0], tid);
    __syncthreads();

    const uint32_t sa[2] = {smem_u32(smA[0]), smem_u32(smA[1])};
    const uint32_t sb[2] = {smem_u32(smB[0]), smem_u32(smB[1])};

    const int T = K / 32;
    for (int t = 0; t < T; t++) {
        const int p = t & 1;
        const bool more = (t + 1 < T);
        if (more) {
            stage_load<AM>(ra, Ab, ldA, row0, (t + 1) * 32, tid);
            stage_load<BM>(rb, Bb, ldB, col0, (t + 1) * 32, tid);
        }
        compute_bk<AM, BM>(sa[p], sb[p], acc, lane, wm, wn);
        if (more) {
            stage_store<AM>(ra, smA[p ^ 1], tid);
            stage_store<BM>(rb, smB[p ^ 1], tid);
            __syncthreads();
        }
    }

    // Epilogue
#pragma unroll
    for (int mb = 0; mb < 4; mb++) {
        const int m0 = row0 + wm + mb * 16 + (lane >> 2);
        const float rb0 = (BIAS == 1) ? bias[m0] : 0.f;
        const float rb1 = (BIAS == 1) ? bias[m0 + 8] : 0.f;
#pragma unroll
        for (int nb = 0; nb < 4; nb++) {
            const int n = col0 + wn + nb * 8 + 2 * (lane & 3);
            float cb0 = 0.f, cb1 = 0.f;
            if (BIAS == 2) { cb0 = bias[n]; cb1 = bias[n + 1]; }
            float v0 = acc[mb][nb][0] * scale + rb0 + cb0;
            float v1 = acc[mb][nb][1] * scale + rb0 + cb1;
            float v2 = acc[mb][nb][2] * scale + rb1 + cb0;
            float v3 = acc[mb][nb][3] * scale + rb1 + cb1;
            if (OUTH) {
                __half* Ch = (__half*)C + (size_t)b * sC;
                *reinterpret_cast<__half2*>(&Ch[(size_t)m0 * ldC + n])       = __floats2half2_rn(v0, v1);
                *reinterpret_cast<__half2*>(&Ch[(size_t)(m0 + 8) * ldC + n]) = __floats2half2_rn(v2, v3);
            } else {
                float* Cf = (float*)C + (size_t)b * sC;
                *reinterpret_cast<float2*>(&Cf[(size_t)m0 * ldC + n])       = make_float2(v0, v1);
                *reinterpret_cast<float2*>(&Cf[(size_t)(m0 + 8) * ldC + n]) = make_float2(v2, v3);
            }
        }
    }
}

// ---------------------------------------------------------------------------
// Row softmax: fp32 scores in, half probs out. 2304 = 256 x 9.
// ---------------------------------------------------------------------------
__global__ __launch_bounds__(256)
void softmax_kernel(const float* __restrict__ S, __half* __restrict__ P)
{
    const float* p = S + blockIdx.x * (size_t)NTOK;
    __half* o = P + blockIdx.x * (size_t)NTOK;
    const int t = threadIdx.x;
    __shared__ float red[256];

    float v[9];
    float m = -INFINITY;
#pragma unroll
    for (int j = 0; j < 9; j++) { v[j] = p[t + j * 256]; m = fmaxf(m, v[j]); }
    red[t] = m; __syncthreads();
    for (int s = 128; s > 0; s >>= 1) {
        if (t < s) red[t] = fmaxf(red[t], red[t + s]);
        __syncthreads();
    }
    m = red[0];
    __syncthreads();

    float sum = 0.f;
#pragma unroll
    for (int j = 0; j < 9; j++) { v[j] = __expf(v[j] - m); sum += v[j]; }
    red[t] = sum; __syncthreads();
    for (int s = 128; s > 0; s >>= 1) {
        if (t < s) red[t] += red[t + s];
        __syncthreads();
    }
    const float inv = 1.0f / red[0];
#pragma unroll
    for (int j = 0; j < 9; j++) o[t + j * 256] = __float2half_rn(v[j] * inv);
}

// ---------------------------------------------------------------------------
extern "C" void kernel_launch(void* const* d_in, const int* in_sizes, int n_in,
                              void* d_out, int out_size)
{
    const float* x  = (const float*)d_in[0];
    const float* Wq = (const float*)d_in[1];
    const float* bq = (const float*)d_in[2];
    const float* Wk = (const float*)d_in[3];
    const float* bk = (const float*)d_in[4];
    const float* Wv = (const float*)d_in[5];
    const float* bv = (const float*)d_in[6];
    const float* Wo = (const float*)d_in[7];
    const float* bo = (const float*)d_in[8];
    float* out = (float*)d_out;

    __half *q, *k, *vt, *p, *ao;
    float* s;
    cudaGetSymbolAddress((void**)&q,  g_q);
    cudaGetSymbolAddress((void**)&k,  g_k);
    cudaGetSymbolAddress((void**)&vt, g_vt);
    cudaGetSymbolAddress((void**)&p,  g_p);
    cudaGetSymbolAddress((void**)&ao, g_ao);
    cudaGetSymbolAddress((void**)&s,  g_s);

    const dim3 blk(NTHREADS);
    const size_t sQKV = (size_t)NTOK * OCH;
    const size_t sS   = (size_t)NTOK * NTOK;
    const size_t sX   = (size_t)CIN * NTOK;
    const float scale = 0.044194173824159216f; // 1/sqrt(512)

    // 1) Q, K: [tok][och] = x^T W^T + b  (A = x f32-trans, B = W f32-NT, col bias)
    {
        dim3 g(OCH / 128, NTOK / 128, BATCH);
        hgemm<2, 1, 1, 2><<<g, blk>>>(x, Wq, q, CIN, NTOK, CIN, OCH, sX, 0, sQKV, bq, 1.0f);
        hgemm<2, 1, 1, 2><<<g, blk>>>(x, Wk, k, CIN, NTOK, CIN, OCH, sX, 0, sQKV, bk, 1.0f);
    }
    // 1b) V^T: [och][tok] = Wv x + bv   (A = Wv f32-NT, B = x f32-trans, row bias)
    {
        dim3 g(NTOK / 128, OCH / 128, BATCH);
        hgemm<1, 2, 1, 1><<<g, blk>>>(Wv, x, vt, CIN, CIN, NTOK, NTOK, 0, sX, sQKV, bv, 1.0f);
    }
    // 2) S = scale * Q K^T  (fp32 out)
    {
        dim3 g(NTOK / 128, NTOK / 128, BATCH);
        hgemm<0, 0, 0, 0><<<g, blk>>>(q, k, s, OCH, OCH, OCH, NTOK, sQKV, sQKV, sS, nullptr, scale);
    }
    // 3) softmax -> half probs
    softmax_kernel<<<BATCH * NTOK, 256>>>(s, p);

    // 4) AO[tok][och] = P V  (A = P f16, B = V^T f16)
    {
        dim3 g(OCH / 128, NTOK / 128, BATCH);
        hgemm<0, 0, 1, 0><<<g, blk>>>(p, vt, ao, NTOK, NTOK, NTOK, OCH, sS, sQKV, sQKV, nullptr, 1.0f);
    }
    // 5) out[och][tok] = Wo AO^T + bo  (A = Wo f32-NT, B = AO f16-NT, fp32 out, row bias)
    {
        dim3 g(NTOK / 128, OCH / 128, BATCH);
        hgemm<1, 0, 0, 1><<<g, blk>>>(Wo, ao, out, OCH, OCH, OCH, NTOK, 0, sQKV, (size_t)OCH * NTOK, bo, 1.0f);
    }
}